// round 1
// baseline (speedup 1.0000x reference)
#include <cuda_runtime.h>
#include <math.h>

#define NSEQ 256
#define CZ   128
#define NH   4
#define HD   32
#define RTOT (NSEQ * NSEQ)   // 65536 pair rows

// Scratch (device globals per harness rules; no runtime allocation)
__device__ float g_Q[(size_t)RTOT * CZ];
__device__ float g_K[(size_t)RTOT * CZ];
__device__ float g_V[(size_t)RTOT * CZ];
__device__ float g_G[(size_t)RTOT * CZ];      // sigmoid already applied
__device__ float g_BiasT[(size_t)NH * RTOT];  // [h][j*256+k]
__device__ float g_AV[(size_t)RTOT * CZ];     // gated attention output

// ---------------------------------------------------------------------------
// Kernel 1: LayerNorm + Q/K/V/G projections + bias projection
// One block = 128 pair-rows. smem: xs[128][129] (padded), ws[128][128].
// ---------------------------------------------------------------------------
__global__ void lnproj_kernel(const float* __restrict__ x,
                              const float* __restrict__ gamma,
                              const float* __restrict__ beta,
                              const float* __restrict__ Wq,
                              const float* __restrict__ Wk,
                              const float* __restrict__ Wv,
                              const float* __restrict__ Wb,
                              const float* __restrict__ Wg,
                              const float* __restrict__ bg)
{
    extern __shared__ float sm[];
    float* xs = sm;               // 128 * 129
    float* ws = sm + 128 * 129;   // 128 * 128
    const int tid = threadIdx.x;
    const size_t r0 = (size_t)blockIdx.x * 128;

    // Load x tile (coalesced float4), store with +1 padding
    const float4* xg = (const float4*)(x + r0 * CZ);
    for (int i = tid; i < 128 * 32; i += 256) {
        float4 v = xg[i];
        int row = i >> 5;
        int c   = (i & 31) << 2;
        float* d = xs + row * 129 + c;
        d[0] = v.x; d[1] = v.y; d[2] = v.z; d[3] = v.w;
    }
    __syncthreads();

    // LayerNorm: one thread per row (threads 0..127)
    if (tid < 128) {
        float* row = xs + tid * 129;
        float s = 0.f, s2 = 0.f;
#pragma unroll 8
        for (int c = 0; c < 128; c++) { float v = row[c]; s += v; s2 += v * v; }
        float mu  = s * (1.f / 128.f);
        float var = s2 * (1.f / 128.f) - mu * mu;
        float inv = rsqrtf(var + 1e-5f);
#pragma unroll 8
        for (int c = 0; c < 128; c++)
            row[c] = (row[c] - mu) * inv * gamma[c] + beta[c];
    }
    __syncthreads();

    // Four 128x128x128 GEMMs: Q, K, V, G(sigmoid(+bg))
    const float* Wm[4] = {Wq, Wk, Wv, Wg};
    float*       Om[4] = {g_Q, g_K, g_V, g_G};
    const int tr = tid >> 4;   // 0..15 row group
    const int tc = tid & 15;   // 0..15 col group

    for (int m = 0; m < 4; m++) {
        for (int i = tid; i < 128 * 32; i += 256)
            ((float4*)ws)[i] = ((const float4*)Wm[m])[i];
        __syncthreads();

        float acc[8][8];
#pragma unroll
        for (int u = 0; u < 8; u++)
#pragma unroll
            for (int v = 0; v < 8; v++) acc[u][v] = 0.f;

#pragma unroll 2
        for (int k = 0; k < 128; k++) {
            float a[8];
#pragma unroll
            for (int u = 0; u < 8; u++) a[u] = xs[(tr * 8 + u) * 129 + k];
            float4 b0 = *(const float4*)(ws + k * 128 + tc * 8);
            float4 b1 = *(const float4*)(ws + k * 128 + tc * 8 + 4);
            float b[8] = {b0.x, b0.y, b0.z, b0.w, b1.x, b1.y, b1.z, b1.w};
#pragma unroll
            for (int u = 0; u < 8; u++)
#pragma unroll
                for (int v = 0; v < 8; v++) acc[u][v] += a[u] * b[v];
        }

        float* O = Om[m] + r0 * CZ;
        if (m == 3) {
            // gating: sigmoid(x@Wg + bg)
#pragma unroll
            for (int u = 0; u < 8; u++) {
                int row = tr * 8 + u;
#pragma unroll
                for (int v = 0; v < 8; v++) {
                    int col = tc * 8 + v;
                    float t = acc[u][v] + bg[col];
                    O[(size_t)row * 128 + col] = 1.f / (1.f + __expf(-t));
                }
            }
        } else {
#pragma unroll
            for (int u = 0; u < 8; u++) {
                int row = tr * 8 + u;
                float4 w0 = make_float4(acc[u][0], acc[u][1], acc[u][2], acc[u][3]);
                float4 w1 = make_float4(acc[u][4], acc[u][5], acc[u][6], acc[u][7]);
                *(float4*)(O + (size_t)row * 128 + tc * 8)     = w0;
                *(float4*)(O + (size_t)row * 128 + tc * 8 + 4) = w1;
            }
        }
        __syncthreads();  // before next W overwrite
    }

    // Bias projection: Wb [128][4] -> g_BiasT[h][r]
    for (int i = tid; i < 512; i += 256) ws[i] = Wb[i];
    __syncthreads();
    for (int o = tid; o < 512; o += 256) {
        int row = o >> 2;
        int h   = o & 3;
        const float* xr = xs + row * 129;
        float s = 0.f;
#pragma unroll 8
        for (int c = 0; c < 128; c++) s += xr[c] * ws[c * 4 + h];
        g_BiasT[(size_t)h * RTOT + r0 + row] = s;
    }
}

// ---------------------------------------------------------------------------
// Kernel 2: attention per (i, h). Block loads K,V [256][32] to smem; each of
// 256 threads owns one j row, online softmax over k, applies gate G.
// ---------------------------------------------------------------------------
__global__ void attn_kernel()
{
    extern __shared__ float sm[];
    float* Ks = sm;               // 256 * 32
    float* Vs = sm + NSEQ * HD;   // 256 * 32
    const int i = blockIdx.x;
    const int h = blockIdx.y;
    const int tid = threadIdx.x;
    const size_t base = ((size_t)i * NSEQ) * CZ + (size_t)h * HD;

    for (int e = tid; e < NSEQ * HD; e += 256) {
        int k = e >> 5, d = e & 31;
        size_t g = base + (size_t)k * CZ + d;
        Ks[e] = g_K[g];
        Vs[e] = g_V[g];
    }
    __syncthreads();

    const int j = tid;
    const float scale = 0.1767766953f; // 1/sqrt(32)
    float q[HD];
    const float4* qp = (const float4*)(g_Q + base + (size_t)j * CZ);
#pragma unroll
    for (int t = 0; t < 8; t++) {
        float4 v = qp[t];
        q[4 * t + 0] = v.x * scale;
        q[4 * t + 1] = v.y * scale;
        q[4 * t + 2] = v.z * scale;
        q[4 * t + 3] = v.w * scale;
    }
    const float* bp = g_BiasT + (size_t)h * RTOT + (size_t)j * NSEQ;

    float m = -1e30f, l = 0.f;
    float acc[HD];
#pragma unroll
    for (int d = 0; d < HD; d++) acc[d] = 0.f;

    for (int k = 0; k < NSEQ; k++) {
        const float* kr = Ks + k * HD;
        float s = bp[k];
#pragma unroll
        for (int d = 0; d < HD; d++) s += q[d] * kr[d];
        const float* vr = Vs + k * HD;
        if (s > m) {
            float corr = __expf(m - s);
            m = s;
            l = l * corr + 1.f;
#pragma unroll
            for (int d = 0; d < HD; d++) acc[d] = acc[d] * corr + vr[d];
        } else {
            float p = __expf(s - m);
            l += p;
#pragma unroll
            for (int d = 0; d < HD; d++) acc[d] += p * vr[d];
        }
    }

    float invl = __fdividef(1.f, l);
    size_t ob = base + (size_t)j * CZ;
#pragma unroll
    for (int d = 0; d < HD; d++)
        g_AV[ob + d] = acc[d] * invl * g_G[ob + d];
}

// ---------------------------------------------------------------------------
// Kernel 3: output projection g_AV @ Wo + bo -> out
// ---------------------------------------------------------------------------
__global__ void outproj_kernel(const float* __restrict__ Wo,
                               const float* __restrict__ bo,
                               float* __restrict__ out)
{
    extern __shared__ float sm[];
    float* as = sm;               // 128 * 129
    float* ws = sm + 128 * 129;   // 128 * 128
    const int tid = threadIdx.x;
    const size_t r0 = (size_t)blockIdx.x * 128;

    const float4* ag = (const float4*)(g_AV + r0 * CZ);
    for (int i = tid; i < 128 * 32; i += 256) {
        float4 v = ag[i];
        int row = i >> 5;
        int c   = (i & 31) << 2;
        float* d = as + row * 129 + c;
        d[0] = v.x; d[1] = v.y; d[2] = v.z; d[3] = v.w;
    }
    for (int i = tid; i < 128 * 32; i += 256)
        ((float4*)ws)[i] = ((const float4*)Wo)[i];
    __syncthreads();

    const int tr = tid >> 4;
    const int tc = tid & 15;
    float acc[8][8];
#pragma unroll
    for (int u = 0; u < 8; u++)
#pragma unroll
        for (int v = 0; v < 8; v++) acc[u][v] = 0.f;

#pragma unroll 2
    for (int k = 0; k < 128; k++) {
        float a[8];
#pragma unroll
        for (int u = 0; u < 8; u++) a[u] = as[(tr * 8 + u) * 129 + k];
        float4 b0 = *(const float4*)(ws + k * 128 + tc * 8);
        float4 b1 = *(const float4*)(ws + k * 128 + tc * 8 + 4);
        float b[8] = {b0.x, b0.y, b0.z, b0.w, b1.x, b1.y, b1.z, b1.w};
#pragma unroll
        for (int u = 0; u < 8; u++)
#pragma unroll
            for (int v = 0; v < 8; v++) acc[u][v] += a[u] * b[v];
    }

    float4 bo0 = *(const float4*)(bo + tc * 8);
    float4 bo1 = *(const float4*)(bo + tc * 8 + 4);
#pragma unroll
    for (int u = 0; u < 8; u++) {
        int row = tr * 8 + u;
        float4 w0 = make_float4(acc[u][0] + bo0.x, acc[u][1] + bo0.y,
                                acc[u][2] + bo0.z, acc[u][3] + bo0.w);
        float4 w1 = make_float4(acc[u][4] + bo1.x, acc[u][5] + bo1.y,
                                acc[u][6] + bo1.z, acc[u][7] + bo1.w);
        *(float4*)(out + ((size_t)(r0 + row)) * 128 + tc * 8)     = w0;
        *(float4*)(out + ((size_t)(r0 + row)) * 128 + tc * 8 + 4) = w1;
    }
}

// ---------------------------------------------------------------------------
extern "C" void kernel_launch(void* const* d_in, const int* in_sizes, int n_in,
                              void* d_out, int out_size)
{
    const float* x     = (const float*)d_in[0];
    const float* gamma = (const float*)d_in[1];
    const float* beta  = (const float*)d_in[2];
    const float* Wq    = (const float*)d_in[3];
    const float* Wk    = (const float*)d_in[4];
    const float* Wv    = (const float*)d_in[5];
    const float* Wb    = (const float*)d_in[6];
    const float* Wg    = (const float*)d_in[7];
    const float* bg    = (const float*)d_in[8];
    const float* Wo    = (const float*)d_in[9];
    const float* bo    = (const float*)d_in[10];
    float* out = (float*)d_out;

    const int smemGemm = (128 * 129 + 128 * 128) * sizeof(float); // 131584
    const int smemAttn = 2 * NSEQ * HD * sizeof(float);           // 65536

    cudaFuncSetAttribute(lnproj_kernel,  cudaFuncAttributeMaxDynamicSharedMemorySize, smemGemm);
    cudaFuncSetAttribute(outproj_kernel, cudaFuncAttributeMaxDynamicSharedMemorySize, smemGemm);
    cudaFuncSetAttribute(attn_kernel,    cudaFuncAttributeMaxDynamicSharedMemorySize, smemAttn);

    lnproj_kernel<<<RTOT / 128, 256, smemGemm>>>(x, gamma, beta, Wq, Wk, Wv, Wb, Wg, bg);

    dim3 g2(NSEQ, NH);
    attn_kernel<<<g2, 256, smemAttn>>>();

    outproj_kernel<<<RTOT / 128, 256, smemGemm>>>(Wo, bo, out);
}

// round 3
// speedup vs baseline: 2.0181x; 2.0181x over previous
#include <cuda_runtime.h>
#include <cuda_bf16.h>
#include <math.h>

#define NSEQ 256
#define CZ   128
#define NH   4
#define HD   32
#define RTOT (NSEQ * NSEQ)

typedef unsigned int u32;
typedef unsigned long long u64;

// ---------------- global scratch ----------------
__device__ float g_Q[(size_t)RTOT * CZ];
__device__ float g_K[(size_t)RTOT * CZ];
__device__ float g_V[(size_t)RTOT * CZ];
__device__ float g_G[(size_t)RTOT * CZ];
__device__ float g_BiasT[(size_t)NH * RTOT];
__device__ float g_AV[(size_t)RTOT * CZ];
// transposed split weights: [w][n][k] bf16, w in {Q,K,V,G,O}
__device__ __nv_bfloat16 g_WtHi[5][CZ * CZ];
__device__ __nv_bfloat16 g_WtLo[5][CZ * CZ];

// ---------------- helpers ----------------
__device__ __forceinline__ u32 smem_u32(const void* p) {
    u32 a;
    asm("{ .reg .u64 t; cvta.to.shared.u64 t, %1; cvt.u32.u64 %0, t; }" : "=r"(a) : "l"(p));
    return a;
}
__device__ __forceinline__ void ldsm_x4(u32* r, u32 addr) {
    asm volatile("ldmatrix.sync.aligned.m8n8.x4.shared.b16 {%0,%1,%2,%3}, [%4];"
        : "=r"(r[0]), "=r"(r[1]), "=r"(r[2]), "=r"(r[3]) : "r"(addr));
}
__device__ __forceinline__ void mma_bf16(float* d, const u32* a, const u32* b) {
    asm volatile("mma.sync.aligned.m16n8k16.row.col.f32.bf16.bf16.f32 "
        "{%0,%1,%2,%3}, {%4,%5,%6,%7}, {%8,%9}, {%0,%1,%2,%3};"
        : "+f"(d[0]), "+f"(d[1]), "+f"(d[2]), "+f"(d[3])
        : "r"(a[0]), "r"(a[1]), "r"(a[2]), "r"(a[3]), "r"(b[0]), "r"(b[1]));
}
// packed f32x2 fma
__device__ __forceinline__ u64 ffma2(u64 a, u64 b, u64 c) {
    u64 d; asm("fma.rn.f32x2 %0, %1, %2, %3;" : "=l"(d) : "l"(a), "l"(b), "l"(c)); return d;
}
__device__ __forceinline__ u64 pk2(float lo, float hi) {
    u64 r; asm("mov.b64 %0, {%1,%2};" : "=l"(r) : "f"(lo), "f"(hi)); return r;
}
__device__ __forceinline__ void up2(u64 v, float& lo, float& hi) {
    asm("mov.b64 {%0,%1}, %2;" : "=f"(lo), "=f"(hi) : "l"(v));
}

// smem layouts (bytes). Row stride 136 bf16 (272 B) -> conflict-free ldmatrix.
#define TSTRIDE 136
#define TBYTES  (128 * TSTRIDE * 2)   // 34816
#define SA_HI 0
#define SA_LO TBYTES
#define SB_HI (2 * TBYTES)
#define SB_LO (3 * TBYTES)
#define SXS   (2 * TBYTES)            // fp32 x-tile overlays B region
#define SWB   (4 * TBYTES)
#define LNP_SMEM (4 * TBYTES + 2048)  // 141312
#define OP_SMEM  (4 * TBYTES)         // 139264

// ---------------------------------------------------------------------------
// Kernel 0: transpose + hi/lo-split weights: B[n][k] = W[k][n]
// ---------------------------------------------------------------------------
__global__ void wtransform(const float* __restrict__ Wq, const float* __restrict__ Wk,
                           const float* __restrict__ Wv, const float* __restrict__ Wg,
                           const float* __restrict__ Wo)
{
    const float* W = (blockIdx.x == 0) ? Wq : (blockIdx.x == 1) ? Wk :
                     (blockIdx.x == 2) ? Wv : (blockIdx.x == 3) ? Wg : Wo;
    __nv_bfloat16* H = g_WtHi[blockIdx.x];
    __nv_bfloat16* L = g_WtLo[blockIdx.x];
    for (int e = threadIdx.x; e < CZ * CZ; e += blockDim.x) {
        int n = e >> 7, c = e & 127;
        float a = W[c * CZ + n];
        __nv_bfloat16 hi = __float2bfloat16(a);
        float lo = a - __bfloat162float(hi);
        H[e] = hi;
        L[e] = __float2bfloat16(lo);
    }
}

// ---------------------------------------------------------------------------
// Kernel 1: LN + Q/K/V/G via mma.sync split-bf16 + bias projection (SIMT)
// ---------------------------------------------------------------------------
__global__ __launch_bounds__(256) void lnproj_mma(const float* __restrict__ x,
                                                  const float* __restrict__ gamma,
                                                  const float* __restrict__ beta,
                                                  const float* __restrict__ Wb,
                                                  const float* __restrict__ bg)
{
    extern __shared__ char sm[];
    const u32 sb = smem_u32(sm);
    const int tid = threadIdx.x, wid = tid >> 5, lane = tid & 31;
    const size_t r0 = (size_t)blockIdx.x * 128;
    float* xs  = (float*)(sm + SXS);   // 128x129 fp32
    float* sWb = (float*)(sm + SWB);

    // 1) load x tile + Wb
    const float4* xg = (const float4*)(x + r0 * CZ);
    for (int i = tid; i < 4096; i += 256) {
        float4 v = xg[i];
        int row = i >> 5, c = (i & 31) << 2;
        float* d = xs + row * 129 + c;
        d[0] = v.x; d[1] = v.y; d[2] = v.z; d[3] = v.w;
    }
    for (int i = tid; i < 512; i += 256) sWb[i] = Wb[i];
    __syncthreads();

    // 2) LayerNorm (one thread per row)
    if (tid < 128) {
        float* row = xs + tid * 129;
        float s = 0.f, s2 = 0.f;
#pragma unroll 8
        for (int c = 0; c < 128; c++) { float v = row[c]; s += v; s2 += v * v; }
        float mu  = s * (1.f / 128.f);
        float var = s2 * (1.f / 128.f) - mu * mu;
        float inv = rsqrtf(var + 1e-5f);
#pragma unroll 8
        for (int c = 0; c < 128; c++)
            row[c] = (row[c] - mu) * inv * gamma[c] + beta[c];
    }
    __syncthreads();

    // 3) bias projection (fp32 exact) + A split conversion
    for (int o = tid; o < 512; o += 256) {
        int row = o >> 2, h = o & 3;
        const float* xr = xs + row * 129;
        float s = 0.f;
#pragma unroll 8
        for (int c = 0; c < 128; c++) s += xr[c] * sWb[c * 4 + h];
        g_BiasT[(size_t)h * RTOT + r0 + row] = s;
    }
    for (int p = tid; p < 8192; p += 256) {
        int row = p >> 6, c = (p & 63) << 1;
        float a0 = xs[row * 129 + c], a1 = xs[row * 129 + c + 1];
        __nv_bfloat16 h0 = __float2bfloat16(a0), h1 = __float2bfloat16(a1);
        __nv_bfloat16 l0 = __float2bfloat16(a0 - __bfloat162float(h0));
        __nv_bfloat16 l1 = __float2bfloat16(a1 - __bfloat162float(h1));
        __nv_bfloat162 hh; hh.x = h0; hh.y = h1;
        __nv_bfloat162 ll; ll.x = l0; ll.y = l1;
        u32 off = (u32)(row * TSTRIDE + c) * 2;
        *(__nv_bfloat162*)(sm + SA_HI + off) = hh;
        *(__nv_bfloat162*)(sm + SA_LO + off) = ll;
    }
    __syncthreads();

    // 4) preload this warp's A fragments (16 rows), hi+lo, all 8 k-steps
    u32 ahi[8][4], alo[8][4];
    {
        int i = lane >> 3, r = lane & 7;
        int arow = wid * 16 + ((i & 1) << 3) + r;
        int acol = (i >> 1) << 3;
        u32 abase = sb + SA_HI + (u32)(arow * TSTRIDE + acol) * 2;
#pragma unroll
        for (int ks = 0; ks < 8; ks++) {
            ldsm_x4(ahi[ks], abase + ks * 32);
            ldsm_x4(alo[ks], abase + TBYTES + ks * 32);
        }
    }

    // B fragment lane addressing (same for all warps)
    const int bi_ = lane >> 3, br = lane & 7;
    const int brow_off = ((bi_ >> 1) << 3) + br;
    const int bcol0 = (bi_ & 1) << 3;
    const int g = lane >> 2, tig = lane & 3;

    // 5) 4 GEMMs
    for (int m = 0; m < 4; m++) {
        // load B hi/lo into smem
        const __nv_bfloat162* shp = (const __nv_bfloat162*)g_WtHi[m];
        const __nv_bfloat162* slp = (const __nv_bfloat162*)g_WtLo[m];
        for (int p = tid; p < 8192; p += 256) {
            int n = p >> 6, k2 = (p & 63) << 1;
            u32 off = (u32)(n * TSTRIDE + k2) * 2;
            *(__nv_bfloat162*)(sm + SB_HI + off) = shp[p];
            *(__nv_bfloat162*)(sm + SB_LO + off) = slp[p];
        }
        __syncthreads();

        float acc[16][4];
#pragma unroll
        for (int t = 0; t < 16; t++)
#pragma unroll
            for (int v = 0; v < 4; v++) acc[t][v] = 0.f;

#pragma unroll
        for (int ks = 0; ks < 8; ks++) {
#pragma unroll
            for (int p = 0; p < 8; p++) {
                u32 ba = sb + SB_HI + (u32)((p * 16 + brow_off) * TSTRIDE + ks * 16 + bcol0) * 2;
                u32 bh[4], bl[4];
                ldsm_x4(bh, ba);
                ldsm_x4(bl, ba + TBYTES);
                mma_bf16(acc[2 * p],     ahi[ks], bh);
                mma_bf16(acc[2 * p + 1], ahi[ks], bh + 2);
                mma_bf16(acc[2 * p],     alo[ks], bh);
                mma_bf16(acc[2 * p + 1], alo[ks], bh + 2);
                mma_bf16(acc[2 * p],     ahi[ks], bl);
                mma_bf16(acc[2 * p + 1], ahi[ks], bl + 2);
            }
        }

        // epilogue
        const size_t rowA = r0 + wid * 16 + g;
        const size_t rowB = rowA + 8;
        if (m < 3) {
            float* O = (m == 0) ? g_Q : (m == 1) ? g_K : g_V;
#pragma unroll
            for (int nt = 0; nt < 16; nt++) {
                int col = nt * 8 + tig * 2;
                *(float2*)(O + rowA * CZ + col) = make_float2(acc[nt][0], acc[nt][1]);
                *(float2*)(O + rowB * CZ + col) = make_float2(acc[nt][2], acc[nt][3]);
            }
        } else {
#pragma unroll
            for (int nt = 0; nt < 16; nt++) {
                int col = nt * 8 + tig * 2;
                float2 bgv = __ldg((const float2*)(bg + col));
                float2 oA, oB;
                oA.x = 1.f / (1.f + __expf(-(acc[nt][0] + bgv.x)));
                oA.y = 1.f / (1.f + __expf(-(acc[nt][1] + bgv.y)));
                oB.x = 1.f / (1.f + __expf(-(acc[nt][2] + bgv.x)));
                oB.y = 1.f / (1.f + __expf(-(acc[nt][3] + bgv.y)));
                *(float2*)(g_G + rowA * CZ + col) = oA;
                *(float2*)(g_G + rowB * CZ + col) = oB;
            }
        }
        __syncthreads();  // before next B overwrite
    }
}

// ---------------------------------------------------------------------------
// Kernel 2: attention, jt=2 + f32x2 packed FMA, no-max softmax (scores bounded)
// ---------------------------------------------------------------------------
#define ATT_SMEM (2 * NSEQ * HD * 4)

__global__ __launch_bounds__(128) void attn_tc()
{
    extern __shared__ float smf[];
    float* Ks = smf;
    float* Vs = smf + NSEQ * HD;
    const int bi = blockIdx.x, h = blockIdx.y, tid = threadIdx.x;
    const size_t base = ((size_t)bi * NSEQ) * CZ + (size_t)h * HD;
    const float scale = 0.17677669529663689f;

    for (int e = tid; e < 2048; e += 128) {
        int row = e >> 3, t = e & 7;
        float4 kv = ((const float4*)(g_K + base + (size_t)row * CZ))[t];
        kv.x *= scale; kv.y *= scale; kv.z *= scale; kv.w *= scale;
        ((float4*)Ks)[e] = kv;
        ((float4*)Vs)[e] = ((const float4*)(g_V + base + (size_t)row * CZ))[t];
    }
    __syncthreads();

    const int j0 = tid, j1 = tid + 128;
    u64 q0[16], q1[16], acc0[16], acc1[16];
    {
        const ulonglong2* qa = (const ulonglong2*)(g_Q + base + (size_t)j0 * CZ);
        const ulonglong2* qb = (const ulonglong2*)(g_Q + base + (size_t)j1 * CZ);
#pragma unroll
        for (int t = 0; t < 8; t++) {
            ulonglong2 a = qa[t]; q0[2 * t] = a.x; q0[2 * t + 1] = a.y;
            ulonglong2 b = qb[t]; q1[2 * t] = b.x; q1[2 * t + 1] = b.y;
        }
    }
#pragma unroll
    for (int t = 0; t < 16; t++) { acc0[t] = 0ull; acc1[t] = 0ull; }

    const float4* bp0 = (const float4*)(g_BiasT + (size_t)h * RTOT + (size_t)j0 * NSEQ);
    const float4* bp1 = (const float4*)(g_BiasT + (size_t)h * RTOT + (size_t)j1 * NSEQ);
    float l0 = 0.f, l1 = 0.f;

    for (int kc = 0; kc < 64; kc++) {
        float4 bb0 = __ldg(bp0 + kc);
        float4 bb1 = __ldg(bp1 + kc);
        float ba0[4] = {bb0.x, bb0.y, bb0.z, bb0.w};
        float ba1[4] = {bb1.x, bb1.y, bb1.z, bb1.w};
#pragma unroll
        for (int u = 0; u < 4; u++) {
            const int k = kc * 4 + u;
            const ulonglong2* kr = (const ulonglong2*)(Ks + k * HD);
            u64 d0a = 0ull, d0b = 0ull, d1a = 0ull, d1b = 0ull;
#pragma unroll
            for (int t = 0; t < 8; t++) {
                ulonglong2 kk = kr[t];
                d0a = ffma2(q0[2 * t],     kk.x, d0a);
                d0b = ffma2(q0[2 * t + 1], kk.y, d0b);
                d1a = ffma2(q1[2 * t],     kk.x, d1a);
                d1b = ffma2(q1[2 * t + 1], kk.y, d1b);
            }
            float x0, x1, x2, x3, y0, y1, y2, y3;
            up2(d0a, x0, x1); up2(d0b, x2, x3);
            up2(d1a, y0, y1); up2(d1b, y2, y3);
            float s0 = ba0[u] + ((x0 + x1) + (x2 + x3));
            float s1 = ba1[u] + ((y0 + y1) + (y2 + y3));
            float p0 = __expf(s0), p1 = __expf(s1);
            l0 += p0; l1 += p1;
            u64 p0p = pk2(p0, p0), p1p = pk2(p1, p1);
            const ulonglong2* vr = (const ulonglong2*)(Vs + k * HD);
#pragma unroll
            for (int t = 0; t < 8; t++) {
                ulonglong2 vv = vr[t];
                acc0[2 * t]     = ffma2(p0p, vv.x, acc0[2 * t]);
                acc0[2 * t + 1] = ffma2(p0p, vv.y, acc0[2 * t + 1]);
                acc1[2 * t]     = ffma2(p1p, vv.x, acc1[2 * t]);
                acc1[2 * t + 1] = ffma2(p1p, vv.y, acc1[2 * t + 1]);
            }
        }
    }

    const float inv0 = __fdividef(1.f, l0);
    const float inv1 = __fdividef(1.f, l1);
    {
        const float4* gp = (const float4*)(g_G + base + (size_t)j0 * CZ);
        float4* op = (float4*)(g_AV + base + (size_t)j0 * CZ);
#pragma unroll
        for (int t = 0; t < 8; t++) {
            float a, b, c, d;
            up2(acc0[2 * t], a, b); up2(acc0[2 * t + 1], c, d);
            float4 gv = gp[t];
            float4 o;
            o.x = a * inv0 * gv.x; o.y = b * inv0 * gv.y;
            o.z = c * inv0 * gv.z; o.w = d * inv0 * gv.w;
            op[t] = o;
        }
    }
    {
        const float4* gp = (const float4*)(g_G + base + (size_t)j1 * CZ);
        float4* op = (float4*)(g_AV + base + (size_t)j1 * CZ);
#pragma unroll
        for (int t = 0; t < 8; t++) {
            float a, b, c, d;
            up2(acc1[2 * t], a, b); up2(acc1[2 * t + 1], c, d);
            float4 gv = gp[t];
            float4 o;
            o.x = a * inv1 * gv.x; o.y = b * inv1 * gv.y;
            o.z = c * inv1 * gv.z; o.w = d * inv1 * gv.w;
            op[t] = o;
        }
    }
}

// ---------------------------------------------------------------------------
// Kernel 3: output projection via mma.sync split-bf16
// ---------------------------------------------------------------------------
__global__ __launch_bounds__(256) void outproj_mma(const float* __restrict__ bo_,
                                                   float* __restrict__ out)
{
    extern __shared__ char sm[];
    const u32 sb = smem_u32(sm);
    const int tid = threadIdx.x, wid = tid >> 5, lane = tid & 31;
    const size_t r0 = (size_t)blockIdx.x * 128;

    // A = g_AV rows -> split bf16 (stride 136)
    for (int p = tid; p < 8192; p += 256) {
        int row = p >> 6, c = (p & 63) << 1;
        float2 v = *(const float2*)(g_AV + (r0 + row) * CZ + c);
        __nv_bfloat16 h0 = __float2bfloat16(v.x), h1 = __float2bfloat16(v.y);
        __nv_bfloat16 l0 = __float2bfloat16(v.x - __bfloat162float(h0));
        __nv_bfloat16 l1 = __float2bfloat16(v.y - __bfloat162float(h1));
        __nv_bfloat162 hh; hh.x = h0; hh.y = h1;
        __nv_bfloat162 ll; ll.x = l0; ll.y = l1;
        u32 off = (u32)(row * TSTRIDE + c) * 2;
        *(__nv_bfloat162*)(sm + SA_HI + off) = hh;
        *(__nv_bfloat162*)(sm + SA_LO + off) = ll;
    }
    // B = Wt[4]
    {
        const __nv_bfloat162* shp = (const __nv_bfloat162*)g_WtHi[4];
        const __nv_bfloat162* slp = (const __nv_bfloat162*)g_WtLo[4];
        for (int p = tid; p < 8192; p += 256) {
            int n = p >> 6, k2 = (p & 63) << 1;
            u32 off = (u32)(n * TSTRIDE + k2) * 2;
            *(__nv_bfloat162*)(sm + SB_HI + off) = shp[p];
            *(__nv_bfloat162*)(sm + SB_LO + off) = slp[p];
        }
    }
    __syncthreads();

    u32 ahi[8][4], alo[8][4];
    {
        int i = lane >> 3, r = lane & 7;
        int arow = wid * 16 + ((i & 1) << 3) + r;
        int acol = (i >> 1) << 3;
        u32 abase = sb + SA_HI + (u32)(arow * TSTRIDE + acol) * 2;
#pragma unroll
        for (int ks = 0; ks < 8; ks++) {
            ldsm_x4(ahi[ks], abase + ks * 32);
            ldsm_x4(alo[ks], abase + TBYTES + ks * 32);
        }
    }

    const int bi_ = lane >> 3, br = lane & 7;
    const int brow_off = ((bi_ >> 1) << 3) + br;
    const int bcol0 = (bi_ & 1) << 3;
    const int g = lane >> 2, tig = lane & 3;

    float acc[16][4];
#pragma unroll
    for (int t = 0; t < 16; t++)
#pragma unroll
        for (int v = 0; v < 4; v++) acc[t][v] = 0.f;

#pragma unroll
    for (int ks = 0; ks < 8; ks++) {
#pragma unroll
        for (int p = 0; p < 8; p++) {
            u32 ba = sb + SB_HI + (u32)((p * 16 + brow_off) * TSTRIDE + ks * 16 + bcol0) * 2;
            u32 bh[4], bl[4];
            ldsm_x4(bh, ba);
            ldsm_x4(bl, ba + TBYTES);
            mma_bf16(acc[2 * p],     ahi[ks], bh);
            mma_bf16(acc[2 * p + 1], ahi[ks], bh + 2);
            mma_bf16(acc[2 * p],     alo[ks], bh);
            mma_bf16(acc[2 * p + 1], alo[ks], bh + 2);
            mma_bf16(acc[2 * p],     ahi[ks], bl);
            mma_bf16(acc[2 * p + 1], ahi[ks], bl + 2);
        }
    }

    const size_t rowA = r0 + wid * 16 + g;
    const size_t rowB = rowA + 8;
#pragma unroll
    for (int nt = 0; nt < 16; nt++) {
        int col = nt * 8 + tig * 2;
        float2 bov = __ldg((const float2*)(bo_ + col));
        *(float2*)(out + rowA * CZ + col) = make_float2(acc[nt][0] + bov.x, acc[nt][1] + bov.y);
        *(float2*)(out + rowB * CZ + col) = make_float2(acc[nt][2] + bov.x, acc[nt][3] + bov.y);
    }
}

// ---------------------------------------------------------------------------
extern "C" void kernel_launch(void* const* d_in, const int* in_sizes, int n_in,
                              void* d_out, int out_size)
{
    const float* x     = (const float*)d_in[0];
    const float* gamma = (const float*)d_in[1];
    const float* beta  = (const float*)d_in[2];
    const float* Wq    = (const float*)d_in[3];
    const float* Wk    = (const float*)d_in[4];
    const float* Wv    = (const float*)d_in[5];
    const float* Wb    = (const float*)d_in[6];
    const float* Wg    = (const float*)d_in[7];
    const float* bg    = (const float*)d_in[8];
    const float* Wo    = (const float*)d_in[9];
    const float* bo    = (const float*)d_in[10];
    float* out = (float*)d_out;

    cudaFuncSetAttribute(lnproj_mma,  cudaFuncAttributeMaxDynamicSharedMemorySize, LNP_SMEM);
    cudaFuncSetAttribute(outproj_mma, cudaFuncAttributeMaxDynamicSharedMemorySize, OP_SMEM);
    cudaFuncSetAttribute(attn_tc,     cudaFuncAttributeMaxDynamicSharedMemorySize, ATT_SMEM);

    wtransform<<<5, 256>>>(Wq, Wk, Wv, Wg, Wo);
    lnproj_mma<<<RTOT / 128, 256, LNP_SMEM>>>(x, gamma, beta, Wb, bg);
    dim3 g2(NSEQ, NH);
    attn_tc<<<g2, 128, ATT_SMEM>>>();
    outproj_mma<<<RTOT / 128, 256, OP_SMEM>>>(bo, out);
}

// round 4
// speedup vs baseline: 3.1356x; 1.5537x over previous
#include <cuda_runtime.h>
#include <cuda_bf16.h>
#include <math.h>

#define NSEQ 256
#define CZ   128
#define NH   4
#define HD   32
#define RTOT (NSEQ * NSEQ)

typedef unsigned int u32;
typedef unsigned long long u64;

// ---------------- global scratch ----------------
__device__ float g_Q[(size_t)RTOT * CZ];
__device__ float g_K[(size_t)RTOT * CZ];
__device__ float g_V[(size_t)RTOT * CZ];
__device__ float g_G[(size_t)RTOT * CZ];
__device__ float g_BiasT[(size_t)NH * RTOT];
__device__ float g_AV[(size_t)RTOT * CZ];
// transposed split weights: [w][n][k] bf16, w in {Q,K,V,G,O}
__device__ __nv_bfloat16 g_WtHi[5][CZ * CZ];
__device__ __nv_bfloat16 g_WtLo[5][CZ * CZ];

// ---------------- helpers ----------------
__device__ __forceinline__ u32 smem_u32(const void* p) {
    u32 a;
    asm("{ .reg .u64 t; cvta.to.shared.u64 t, %1; cvt.u32.u64 %0, t; }" : "=r"(a) : "l"(p));
    return a;
}
__device__ __forceinline__ void ldsm_x4(u32* r, u32 addr) {
    asm volatile("ldmatrix.sync.aligned.m8n8.x4.shared.b16 {%0,%1,%2,%3}, [%4];"
        : "=r"(r[0]), "=r"(r[1]), "=r"(r[2]), "=r"(r[3]) : "r"(addr));
}
__device__ __forceinline__ void mma_bf16(float* d, const u32* a, const u32* b) {
    asm volatile("mma.sync.aligned.m16n8k16.row.col.f32.bf16.bf16.f32 "
        "{%0,%1,%2,%3}, {%4,%5,%6,%7}, {%8,%9}, {%0,%1,%2,%3};"
        : "+f"(d[0]), "+f"(d[1]), "+f"(d[2]), "+f"(d[3])
        : "r"(a[0]), "r"(a[1]), "r"(a[2]), "r"(a[3]), "r"(b[0]), "r"(b[1]));
}
__device__ __forceinline__ u32 pack_bf2(float x, float y) {
    __nv_bfloat162 t;
    t.x = __float2bfloat16(x);
    t.y = __float2bfloat16(y);
    return *(u32*)&t;
}

// smem layouts for GEMM kernels (bytes). Row stride 136 bf16 -> conflict-free ldmatrix.
#define TSTRIDE 136
#define TBYTES  (128 * TSTRIDE * 2)   // 34816
#define SA_HI 0
#define SA_LO TBYTES
#define SB_HI (2 * TBYTES)
#define SB_LO (3 * TBYTES)
#define SXS   (2 * TBYTES)
#define SWB   (4 * TBYTES)
#define LNP_SMEM (4 * TBYTES + 2048)
#define OP_SMEM  (4 * TBYTES)

// ---------------------------------------------------------------------------
// Kernel 0: transpose + hi/lo-split weights: B[n][k] = W[k][n]
// ---------------------------------------------------------------------------
__global__ void wtransform(const float* __restrict__ Wq, const float* __restrict__ Wk,
                           const float* __restrict__ Wv, const float* __restrict__ Wg,
                           const float* __restrict__ Wo)
{
    const float* W = (blockIdx.x == 0) ? Wq : (blockIdx.x == 1) ? Wk :
                     (blockIdx.x == 2) ? Wv : (blockIdx.x == 3) ? Wg : Wo;
    __nv_bfloat16* H = g_WtHi[blockIdx.x];
    __nv_bfloat16* L = g_WtLo[blockIdx.x];
    for (int e = threadIdx.x; e < CZ * CZ; e += blockDim.x) {
        int n = e >> 7, c = e & 127;
        float a = W[c * CZ + n];
        __nv_bfloat16 hi = __float2bfloat16(a);
        float lo = a - __bfloat162float(hi);
        H[e] = hi;
        L[e] = __float2bfloat16(lo);
    }
}

// ---------------------------------------------------------------------------
// Kernel 1: LN + Q/K/V/G via mma.sync split-bf16 + bias projection (SIMT)
// ---------------------------------------------------------------------------
__global__ __launch_bounds__(256) void lnproj_mma(const float* __restrict__ x,
                                                  const float* __restrict__ gamma,
                                                  const float* __restrict__ beta,
                                                  const float* __restrict__ Wb,
                                                  const float* __restrict__ bg)
{
    extern __shared__ char sm[];
    const u32 sb = smem_u32(sm);
    const int tid = threadIdx.x, wid = tid >> 5, lane = tid & 31;
    const size_t r0 = (size_t)blockIdx.x * 128;
    float* xs  = (float*)(sm + SXS);
    float* sWb = (float*)(sm + SWB);

    const float4* xg = (const float4*)(x + r0 * CZ);
    for (int i = tid; i < 4096; i += 256) {
        float4 v = xg[i];
        int row = i >> 5, c = (i & 31) << 2;
        float* d = xs + row * 129 + c;
        d[0] = v.x; d[1] = v.y; d[2] = v.z; d[3] = v.w;
    }
    for (int i = tid; i < 512; i += 256) sWb[i] = Wb[i];
    __syncthreads();

    if (tid < 128) {
        float* row = xs + tid * 129;
        float s = 0.f, s2 = 0.f;
#pragma unroll 8
        for (int c = 0; c < 128; c++) { float v = row[c]; s += v; s2 += v * v; }
        float mu  = s * (1.f / 128.f);
        float var = s2 * (1.f / 128.f) - mu * mu;
        float inv = rsqrtf(var + 1e-5f);
#pragma unroll 8
        for (int c = 0; c < 128; c++)
            row[c] = (row[c] - mu) * inv * gamma[c] + beta[c];
    }
    __syncthreads();

    for (int o = tid; o < 512; o += 256) {
        int row = o >> 2, h = o & 3;
        const float* xr = xs + row * 129;
        float s = 0.f;
#pragma unroll 8
        for (int c = 0; c < 128; c++) s += xr[c] * sWb[c * 4 + h];
        g_BiasT[(size_t)h * RTOT + r0 + row] = s;
    }
    for (int p = tid; p < 8192; p += 256) {
        int row = p >> 6, c = (p & 63) << 1;
        float a0 = xs[row * 129 + c], a1 = xs[row * 129 + c + 1];
        __nv_bfloat16 h0 = __float2bfloat16(a0), h1 = __float2bfloat16(a1);
        __nv_bfloat16 l0 = __float2bfloat16(a0 - __bfloat162float(h0));
        __nv_bfloat16 l1 = __float2bfloat16(a1 - __bfloat162float(h1));
        __nv_bfloat162 hh; hh.x = h0; hh.y = h1;
        __nv_bfloat162 ll; ll.x = l0; ll.y = l1;
        u32 off = (u32)(row * TSTRIDE + c) * 2;
        *(__nv_bfloat162*)(sm + SA_HI + off) = hh;
        *(__nv_bfloat162*)(sm + SA_LO + off) = ll;
    }
    __syncthreads();

    u32 ahi[8][4], alo[8][4];
    {
        int i = lane >> 3, r = lane & 7;
        int arow = wid * 16 + ((i & 1) << 3) + r;
        int acol = (i >> 1) << 3;
        u32 abase = sb + SA_HI + (u32)(arow * TSTRIDE + acol) * 2;
#pragma unroll
        for (int ks = 0; ks < 8; ks++) {
            ldsm_x4(ahi[ks], abase + ks * 32);
            ldsm_x4(alo[ks], abase + TBYTES + ks * 32);
        }
    }

    const int bi_ = lane >> 3, br = lane & 7;
    const int brow_off = ((bi_ >> 1) << 3) + br;
    const int bcol0 = (bi_ & 1) << 3;
    const int g = lane >> 2, tig = lane & 3;

    for (int m = 0; m < 4; m++) {
        const __nv_bfloat162* shp = (const __nv_bfloat162*)g_WtHi[m];
        const __nv_bfloat162* slp = (const __nv_bfloat162*)g_WtLo[m];
        for (int p = tid; p < 8192; p += 256) {
            int n = p >> 6, k2 = (p & 63) << 1;
            u32 off = (u32)(n * TSTRIDE + k2) * 2;
            *(__nv_bfloat162*)(sm + SB_HI + off) = shp[p];
            *(__nv_bfloat162*)(sm + SB_LO + off) = slp[p];
        }
        __syncthreads();

        float acc[16][4];
#pragma unroll
        for (int t = 0; t < 16; t++)
#pragma unroll
            for (int v = 0; v < 4; v++) acc[t][v] = 0.f;

#pragma unroll
        for (int ks = 0; ks < 8; ks++) {
#pragma unroll
            for (int p = 0; p < 8; p++) {
                u32 ba = sb + SB_HI + (u32)((p * 16 + brow_off) * TSTRIDE + ks * 16 + bcol0) * 2;
                u32 bh[4], bl[4];
                ldsm_x4(bh, ba);
                ldsm_x4(bl, ba + TBYTES);
                mma_bf16(acc[2 * p],     ahi[ks], bh);
                mma_bf16(acc[2 * p + 1], ahi[ks], bh + 2);
                mma_bf16(acc[2 * p],     alo[ks], bh);
                mma_bf16(acc[2 * p + 1], alo[ks], bh + 2);
                mma_bf16(acc[2 * p],     ahi[ks], bl);
                mma_bf16(acc[2 * p + 1], ahi[ks], bl + 2);
            }
        }

        const size_t rowA = r0 + wid * 16 + g;
        const size_t rowB = rowA + 8;
        if (m < 3) {
            float* O = (m == 0) ? g_Q : (m == 1) ? g_K : g_V;
#pragma unroll
            for (int nt = 0; nt < 16; nt++) {
                int col = nt * 8 + tig * 2;
                *(float2*)(O + rowA * CZ + col) = make_float2(acc[nt][0], acc[nt][1]);
                *(float2*)(O + rowB * CZ + col) = make_float2(acc[nt][2], acc[nt][3]);
            }
        } else {
#pragma unroll
            for (int nt = 0; nt < 16; nt++) {
                int col = nt * 8 + tig * 2;
                float2 bgv = __ldg((const float2*)(bg + col));
                float2 oA, oB;
                oA.x = 1.f / (1.f + __expf(-(acc[nt][0] + bgv.x)));
                oA.y = 1.f / (1.f + __expf(-(acc[nt][1] + bgv.y)));
                oB.x = 1.f / (1.f + __expf(-(acc[nt][2] + bgv.x)));
                oB.y = 1.f / (1.f + __expf(-(acc[nt][3] + bgv.y)));
                *(float2*)(g_G + rowA * CZ + col) = oA;
                *(float2*)(g_G + rowB * CZ + col) = oB;
            }
        }
        __syncthreads();
    }
}

// ---------------------------------------------------------------------------
// Kernel 2: attention via mma.sync split-bf16, flash-style, no-max softmax.
// Grid (256, 8): blockIdx.x = i, blockIdx.y = h*2 + jhalf. 8 warps x 16 j-rows.
// ---------------------------------------------------------------------------
#define AT_KHI 0
#define AT_KLO 20480                  // 256*40*2
#define AT_VHI 40960
#define AT_VLO (40960 + 16896)        // 32*264*2
#define AT_SMEM (40960 + 2 * 16896)   // 74752
#define KSTR 40
#define VSTR 264

__global__ __launch_bounds__(256, 2) void attn_mma()
{
    extern __shared__ char sm[];
    const u32 sb = smem_u32(sm);
    const int tid = threadIdx.x, wid = tid >> 5, lane = tid & 31;
    const int bi = blockIdx.x;
    const int h  = blockIdx.y >> 1;
    const int jh = blockIdx.y & 1;
    const size_t base = ((size_t)bi * NSEQ) * CZ + (size_t)h * HD;

    // ---- stage K (split) and V^T (split) ----
    __nv_bfloat16* KhiS = (__nv_bfloat16*)(sm + AT_KHI);
    __nv_bfloat16* KloS = (__nv_bfloat16*)(sm + AT_KLO);
    __nv_bfloat16* VhiS = (__nv_bfloat16*)(sm + AT_VHI);
    __nv_bfloat16* VloS = (__nv_bfloat16*)(sm + AT_VLO);

    for (int e = tid; e < 2048; e += 256) {
        int k = e >> 3, d4 = (e & 7) << 2;
        float4 kv = *(const float4*)(g_K + base + (size_t)k * CZ + d4);
        float4 vv = *(const float4*)(g_V + base + (size_t)k * CZ + d4);
        float kf[4] = {kv.x, kv.y, kv.z, kv.w};
        float vf[4] = {vv.x, vv.y, vv.z, vv.w};
#pragma unroll
        for (int m = 0; m < 4; m++) {
            __nv_bfloat16 kh = __float2bfloat16(kf[m]);
            KhiS[k * KSTR + d4 + m] = kh;
            KloS[k * KSTR + d4 + m] = __float2bfloat16(kf[m] - __bfloat162float(kh));
            __nv_bfloat16 vh = __float2bfloat16(vf[m]);
            VhiS[(d4 + m) * VSTR + k] = vh;
            VloS[(d4 + m) * VSTR + k] = __float2bfloat16(vf[m] - __bfloat162float(vh));
        }
    }
    __syncthreads();

    const int jr = jh * 128 + wid * 16;          // warp's j base
    const int r  = lane >> 2, c2 = (lane & 3) << 1;
    const float scale = 0.17677669529663689f;

    // ---- Q fragments (split), scaled ----
    u32 qhi[2][4], qlo[2][4];
#pragma unroll
    for (int ks = 0; ks < 2; ks++)
#pragma unroll
        for (int reg = 0; reg < 4; reg++) {
            int row = jr + r + (reg & 1) * 8;
            int col = ks * 16 + c2 + ((reg >> 1) << 3);
            float2 qv = *(const float2*)(g_Q + base + (size_t)row * CZ + col);
            qv.x *= scale; qv.y *= scale;
            float hx = __bfloat162float(__float2bfloat16(qv.x));
            float hy = __bfloat162float(__float2bfloat16(qv.y));
            qhi[ks][reg] = pack_bf2(qv.x, qv.y);
            qlo[ks][reg] = pack_bf2(qv.x - hx, qv.y - hy);
        }

    const int i_ = lane >> 3, r_ = lane & 7;
    const int brow = ((i_ >> 1) << 3) + r_;
    const int bcol = (i_ & 1) << 3;

    float oacc[4][4];
#pragma unroll
    for (int t = 0; t < 4; t++)
#pragma unroll
        for (int v = 0; v < 4; v++) oacc[t][v] = 0.f;
    float lsum0 = 0.f, lsum1 = 0.f;

    const float* bias0 = g_BiasT + (size_t)h * RTOT + (size_t)(jr + r) * NSEQ;
    const float* bias1 = bias0 + 8 * NSEQ;

    for (int kc = 0; kc < 4; kc++) {
        float sacc[8][4];
#pragma unroll
        for (int t = 0; t < 8; t++)
#pragma unroll
            for (int v = 0; v < 4; v++) sacc[t][v] = 0.f;

        // ---- S = Q K^T (3-term split) ----
#pragma unroll
        for (int p4 = 0; p4 < 4; p4++) {
#pragma unroll
            for (int ks = 0; ks < 2; ks++) {
                u32 addr = sb + AT_KHI + (u32)((kc * 64 + p4 * 16 + brow) * KSTR + ks * 16 + bcol) * 2;
                u32 bh[4], bl[4];
                ldsm_x4(bh, addr);
                ldsm_x4(bl, addr + (AT_KLO - AT_KHI));
                mma_bf16(sacc[2 * p4],     qhi[ks], bh);
                mma_bf16(sacc[2 * p4 + 1], qhi[ks], bh + 2);
                mma_bf16(sacc[2 * p4],     qlo[ks], bh);
                mma_bf16(sacc[2 * p4 + 1], qlo[ks], bh + 2);
                mma_bf16(sacc[2 * p4],     qhi[ks], bl);
                mma_bf16(sacc[2 * p4 + 1], qhi[ks], bl + 2);
            }
        }

        // ---- bias + exp (no-max: scores bounded) + row sums ----
#pragma unroll
        for (int nt = 0; nt < 8; nt++) {
            int kcol = kc * 64 + nt * 8 + c2;
            float2 b0 = __ldg((const float2*)(bias0 + kcol));
            float2 b1 = __ldg((const float2*)(bias1 + kcol));
            float p00 = __expf(sacc[nt][0] + b0.x);
            float p01 = __expf(sacc[nt][1] + b0.y);
            float p10 = __expf(sacc[nt][2] + b1.x);
            float p11 = __expf(sacc[nt][3] + b1.y);
            sacc[nt][0] = p00; sacc[nt][1] = p01;
            sacc[nt][2] = p10; sacc[nt][3] = p11;
            lsum0 += p00 + p01;
            lsum1 += p10 + p11;
        }

        // ---- O += P V (3-term split; P repacked from S fragments) ----
#pragma unroll
        for (int ks2 = 0; ks2 < 4; ks2++) {
            u32 phi[4], plo[4];
            {
                const float* s0 = sacc[2 * ks2];
                const float* s1 = sacc[2 * ks2 + 1];
                float h00 = __bfloat162float(__float2bfloat16(s0[0]));
                float h01 = __bfloat162float(__float2bfloat16(s0[1]));
                float h02 = __bfloat162float(__float2bfloat16(s0[2]));
                float h03 = __bfloat162float(__float2bfloat16(s0[3]));
                float h10 = __bfloat162float(__float2bfloat16(s1[0]));
                float h11 = __bfloat162float(__float2bfloat16(s1[1]));
                float h12 = __bfloat162float(__float2bfloat16(s1[2]));
                float h13 = __bfloat162float(__float2bfloat16(s1[3]));
                phi[0] = pack_bf2(s0[0], s0[1]);
                phi[1] = pack_bf2(s0[2], s0[3]);
                phi[2] = pack_bf2(s1[0], s1[1]);
                phi[3] = pack_bf2(s1[2], s1[3]);
                plo[0] = pack_bf2(s0[0] - h00, s0[1] - h01);
                plo[1] = pack_bf2(s0[2] - h02, s0[3] - h03);
                plo[2] = pack_bf2(s1[0] - h10, s1[1] - h11);
                plo[3] = pack_bf2(s1[2] - h12, s1[3] - h13);
            }
            u32 vh[8], vl[8];
            u32 a0 = sb + AT_VHI + (u32)(brow * VSTR + kc * 64 + ks2 * 16 + bcol) * 2;
            u32 a1 = sb + AT_VHI + (u32)((brow + 16) * VSTR + kc * 64 + ks2 * 16 + bcol) * 2;
            ldsm_x4(vh,     a0);
            ldsm_x4(vh + 4, a1);
            ldsm_x4(vl,     a0 + (AT_VLO - AT_VHI));
            ldsm_x4(vl + 4, a1 + (AT_VLO - AT_VHI));
#pragma unroll
            for (int ntd = 0; ntd < 4; ntd++) {
                mma_bf16(oacc[ntd], phi, vh + 2 * ntd);
                mma_bf16(oacc[ntd], plo, vh + 2 * ntd);
                mma_bf16(oacc[ntd], phi, vl + 2 * ntd);
            }
        }
    }

    // ---- reduce row sums across the quad (lanes sharing t/4) ----
    lsum0 += __shfl_xor_sync(0xFFFFFFFF, lsum0, 1);
    lsum0 += __shfl_xor_sync(0xFFFFFFFF, lsum0, 2);
    lsum1 += __shfl_xor_sync(0xFFFFFFFF, lsum1, 1);
    lsum1 += __shfl_xor_sync(0xFFFFFFFF, lsum1, 2);
    const float inv0 = __fdividef(1.f, lsum0);
    const float inv1 = __fdividef(1.f, lsum1);

    // ---- gate + write ----
    const size_t row0 = base + (size_t)(jr + r) * CZ;
    const size_t row1 = row0 + 8 * CZ;
#pragma unroll
    for (int ntd = 0; ntd < 4; ntd++) {
        int col = ntd * 8 + c2;
        float2 g0 = __ldg((const float2*)(g_G + row0 + col));
        float2 g1 = __ldg((const float2*)(g_G + row1 + col));
        float2 o0, o1;
        o0.x = oacc[ntd][0] * inv0 * g0.x;
        o0.y = oacc[ntd][1] * inv0 * g0.y;
        o1.x = oacc[ntd][2] * inv1 * g1.x;
        o1.y = oacc[ntd][3] * inv1 * g1.y;
        *(float2*)(g_AV + row0 + col) = o0;
        *(float2*)(g_AV + row1 + col) = o1;
    }
}

// ---------------------------------------------------------------------------
// Kernel 3: output projection via mma.sync split-bf16
// ---------------------------------------------------------------------------
__global__ __launch_bounds__(256) void outproj_mma(const float* __restrict__ bo_,
                                                   float* __restrict__ out)
{
    extern __shared__ char sm[];
    const u32 sb = smem_u32(sm);
    const int tid = threadIdx.x, wid = tid >> 5, lane = tid & 31;
    const size_t r0 = (size_t)blockIdx.x * 128;

    for (int p = tid; p < 8192; p += 256) {
        int row = p >> 6, c = (p & 63) << 1;
        float2 v = *(const float2*)(g_AV + (r0 + row) * CZ + c);
        __nv_bfloat16 h0 = __float2bfloat16(v.x), h1 = __float2bfloat16(v.y);
        __nv_bfloat16 l0 = __float2bfloat16(v.x - __bfloat162float(h0));
        __nv_bfloat16 l1 = __float2bfloat16(v.y - __bfloat162float(h1));
        __nv_bfloat162 hh; hh.x = h0; hh.y = h1;
        __nv_bfloat162 ll; ll.x = l0; ll.y = l1;
        u32 off = (u32)(row * TSTRIDE + c) * 2;
        *(__nv_bfloat162*)(sm + SA_HI + off) = hh;
        *(__nv_bfloat162*)(sm + SA_LO + off) = ll;
    }
    {
        const __nv_bfloat162* shp = (const __nv_bfloat162*)g_WtHi[4];
        const __nv_bfloat162* slp = (const __nv_bfloat162*)g_WtLo[4];
        for (int p = tid; p < 8192; p += 256) {
            int n = p >> 6, k2 = (p & 63) << 1;
            u32 off = (u32)(n * TSTRIDE + k2) * 2;
            *(__nv_bfloat162*)(sm + SB_HI + off) = shp[p];
            *(__nv_bfloat162*)(sm + SB_LO + off) = slp[p];
        }
    }
    __syncthreads();

    u32 ahi[8][4], alo[8][4];
    {
        int i = lane >> 3, r = lane & 7;
        int arow = wid * 16 + ((i & 1) << 3) + r;
        int acol = (i >> 1) << 3;
        u32 abase = sb + SA_HI + (u32)(arow * TSTRIDE + acol) * 2;
#pragma unroll
        for (int ks = 0; ks < 8; ks++) {
            ldsm_x4(ahi[ks], abase + ks * 32);
            ldsm_x4(alo[ks], abase + TBYTES + ks * 32);
        }
    }

    const int bi_ = lane >> 3, br = lane & 7;
    const int brow_off = ((bi_ >> 1) << 3) + br;
    const int bcol0 = (bi_ & 1) << 3;
    const int g = lane >> 2, tig = lane & 3;

    float acc[16][4];
#pragma unroll
    for (int t = 0; t < 16; t++)
#pragma unroll
        for (int v = 0; v < 4; v++) acc[t][v] = 0.f;

#pragma unroll
    for (int ks = 0; ks < 8; ks++) {
#pragma unroll
        for (int p = 0; p < 8; p++) {
            u32 ba = sb + SB_HI + (u32)((p * 16 + brow_off) * TSTRIDE + ks * 16 + bcol0) * 2;
            u32 bh[4], bl[4];
            ldsm_x4(bh, ba);
            ldsm_x4(bl, ba + TBYTES);
            mma_bf16(acc[2 * p],     ahi[ks], bh);
            mma_bf16(acc[2 * p + 1], ahi[ks], bh + 2);
            mma_bf16(acc[2 * p],     alo[ks], bh);
            mma_bf16(acc[2 * p + 1], alo[ks], bh + 2);
            mma_bf16(acc[2 * p],     ahi[ks], bl);
            mma_bf16(acc[2 * p + 1], ahi[ks], bl + 2);
        }
    }

    const size_t rowA = r0 + wid * 16 + g;
    const size_t rowB = rowA + 8;
#pragma unroll
    for (int nt = 0; nt < 16; nt++) {
        int col = nt * 8 + tig * 2;
        float2 bov = __ldg((const float2*)(bo_ + col));
        *(float2*)(out + rowA * CZ + col) = make_float2(acc[nt][0] + bov.x, acc[nt][1] + bov.y);
        *(float2*)(out + rowB * CZ + col) = make_float2(acc[nt][2] + bov.x, acc[nt][3] + bov.y);
    }
}

// ---------------------------------------------------------------------------
extern "C" void kernel_launch(void* const* d_in, const int* in_sizes, int n_in,
                              void* d_out, int out_size)
{
    const float* x     = (const float*)d_in[0];
    const float* gamma = (const float*)d_in[1];
    const float* beta  = (const float*)d_in[2];
    const float* Wq    = (const float*)d_in[3];
    const float* Wk    = (const float*)d_in[4];
    const float* Wv    = (const float*)d_in[5];
    const float* Wb    = (const float*)d_in[6];
    const float* Wg    = (const float*)d_in[7];
    const float* bg    = (const float*)d_in[8];
    const float* Wo    = (const float*)d_in[9];
    const float* bo    = (const float*)d_in[10];
    float* out = (float*)d_out;

    cudaFuncSetAttribute(lnproj_mma,  cudaFuncAttributeMaxDynamicSharedMemorySize, LNP_SMEM);
    cudaFuncSetAttribute(outproj_mma, cudaFuncAttributeMaxDynamicSharedMemorySize, OP_SMEM);
    cudaFuncSetAttribute(attn_mma,    cudaFuncAttributeMaxDynamicSharedMemorySize, AT_SMEM);

    wtransform<<<5, 256>>>(Wq, Wk, Wv, Wg, Wo);
    lnproj_mma<<<RTOT / 128, 256, LNP_SMEM>>>(x, gamma, beta, Wb, bg);
    dim3 g2(NSEQ, 2 * NH);
    attn_mma<<<g2, 256, AT_SMEM>>>();
    outproj_mma<<<RTOT / 128, 256, OP_SMEM>>>(bo, out);
}

// round 5
// speedup vs baseline: 3.6156x; 1.1531x over previous
#include <cuda_runtime.h>
#include <cuda_bf16.h>
#include <math.h>

#define NSEQ 256
#define CZ   128
#define NH   4
#define HD   32
#define RTOT (NSEQ * NSEQ)

typedef unsigned int u32;
typedef unsigned long long u64;

// ---------------- global scratch ----------------
__device__ float g_Q[(size_t)RTOT * CZ];
__device__ float g_K[(size_t)RTOT * CZ];
__device__ float g_V[(size_t)RTOT * CZ];
__device__ float g_G[(size_t)RTOT * CZ];
__device__ float g_BiasT[(size_t)NH * RTOT];
__device__ float g_AV[(size_t)RTOT * CZ];
// transposed split weights: [w][n][k] bf16, w in {Q,K,V,G,O}
__device__ __nv_bfloat16 g_WtHi[5][CZ * CZ];
__device__ __nv_bfloat16 g_WtLo[5][CZ * CZ];

// ---------------- helpers ----------------
__device__ __forceinline__ u32 smem_u32(const void* p) {
    u32 a;
    asm("{ .reg .u64 t; cvta.to.shared.u64 t, %1; cvt.u32.u64 %0, t; }" : "=r"(a) : "l"(p));
    return a;
}
__device__ __forceinline__ void ldsm_x4(u32* r, u32 addr) {
    asm volatile("ldmatrix.sync.aligned.m8n8.x4.shared.b16 {%0,%1,%2,%3}, [%4];"
        : "=r"(r[0]), "=r"(r[1]), "=r"(r[2]), "=r"(r[3]) : "r"(addr));
}
__device__ __forceinline__ void mma_bf16(float* d, const u32* a, const u32* b) {
    asm volatile("mma.sync.aligned.m16n8k16.row.col.f32.bf16.bf16.f32 "
        "{%0,%1,%2,%3}, {%4,%5,%6,%7}, {%8,%9}, {%0,%1,%2,%3};"
        : "+f"(d[0]), "+f"(d[1]), "+f"(d[2]), "+f"(d[3])
        : "r"(a[0]), "r"(a[1]), "r"(a[2]), "r"(a[3]), "r"(b[0]), "r"(b[1]));
}
__device__ __forceinline__ u32 pack_bf2(float x, float y) {
    __nv_bfloat162 t;
    t.x = __float2bfloat16(x);
    t.y = __float2bfloat16(y);
    return *(u32*)&t;
}
__device__ __forceinline__ void cp16(u32 dst, const void* src) {
    u64 g;
    asm("cvta.to.global.u64 %0, %1;" : "=l"(g) : "l"(src));
    asm volatile("cp.async.ca.shared.global [%0], [%1], 16;" :: "r"(dst), "l"(g));
}
#define CP_COMMIT() asm volatile("cp.async.commit_group;")
#define CP_WAIT(n)  asm volatile("cp.async.wait_group %0;" :: "n"(n))

// bf16 tile: 128 rows x 136 stride (conflict-free ldmatrix), 34816 B per half
#define TSTRIDE 136
#define THALF   34816

// lnproj smem layout (bytes)
#define LNP_SA   0                  // A hi | A lo  (69632)
#define LNP_SB0  69632              // B buf0 hi|lo (69632)
#define LNP_SB1  139264             // B buf1 hi|lo (69632)
#define LNP_XS   69632              // fp32 x-tile overlays SB0 (66048)
#define LNP_WB   (69632 + 66048)    // Wb (2048) still inside SB0
#define LNP_SMEM 208896

// outproj smem layout
#define OP_SA   0
#define OP_SB   69632
#define OP_SMEM 139264

// ---------------------------------------------------------------------------
// Kernel 0: transpose + hi/lo-split weights: B[n][k] = W[k][n]
// ---------------------------------------------------------------------------
__global__ void wtransform(const float* __restrict__ Wq, const float* __restrict__ Wk,
                           const float* __restrict__ Wv, const float* __restrict__ Wg,
                           const float* __restrict__ Wo)
{
    const float* W = (blockIdx.x == 0) ? Wq : (blockIdx.x == 1) ? Wk :
                     (blockIdx.x == 2) ? Wv : (blockIdx.x == 3) ? Wg : Wo;
    __nv_bfloat16* H = g_WtHi[blockIdx.x];
    __nv_bfloat16* L = g_WtLo[blockIdx.x];
    for (int e = threadIdx.x; e < CZ * CZ; e += blockDim.x) {
        int n = e >> 7, c = e & 127;
        float a = W[c * CZ + n];
        __nv_bfloat16 hi = __float2bfloat16(a);
        float lo = a - __bfloat162float(hi);
        H[e] = hi;
        L[e] = __float2bfloat16(lo);
    }
}

// ---------------------------------------------------------------------------
// GEMM warp mainloop: 16 rows x 64 cols per warp, A reloaded per ks (no spill)
// aBase points at (arow*TSTRIDE + acol0)*2 inside A-hi; bBase likewise in B-hi.
// ---------------------------------------------------------------------------
__device__ __forceinline__ void gemm_warp(float acc[8][4], u32 aBase, u32 bBase)
{
#pragma unroll
    for (int ks = 0; ks < 8; ks++) {
        u32 ah[4], al[4];
        ldsm_x4(ah, aBase + ks * 32);
        ldsm_x4(al, aBase + THALF + ks * 32);
#pragma unroll
        for (int p = 0; p < 4; p++) {
            u32 ba = bBase + (u32)(p * 16 * TSTRIDE) * 2 + ks * 32;
            u32 bh[4], bl[4];
            ldsm_x4(bh, ba);
            ldsm_x4(bl, ba + THALF);
            mma_bf16(acc[2 * p],     ah, bh);
            mma_bf16(acc[2 * p + 1], ah, bh + 2);
            mma_bf16(acc[2 * p],     al, bh);
            mma_bf16(acc[2 * p + 1], al, bh + 2);
            mma_bf16(acc[2 * p],     ah, bl);
            mma_bf16(acc[2 * p + 1], ah, bl + 2);
        }
    }
}

// async-copy one weight matrix (hi+lo) into smem buffer (512 threads)
__device__ __forceinline__ void cp_weights(u32 sb, u32 bufOff, int m, int tid)
{
    for (int e = tid; e < 4096; e += 512) {
        int half = e >> 11, rem = e & 2047, n = rem >> 4, ch = rem & 15;
        const __nv_bfloat16* src = (half ? g_WtLo[m] : g_WtHi[m]) + n * 128 + ch * 8;
        u32 dst = sb + bufOff + (u32)half * THALF + (u32)(n * TSTRIDE + ch * 8) * 2;
        cp16(dst, src);
    }
    CP_COMMIT();
}

// ---------------------------------------------------------------------------
// Kernel 1: LN + Q/K/V/G via mma.sync split-bf16, cp.async double-buffered B
// 512 threads: warps 8x2 (wr 0..7 rows, wc 0..1 col-half)
// ---------------------------------------------------------------------------
__global__ __launch_bounds__(512) void lnproj_mma(const float* __restrict__ x,
                                                  const float* __restrict__ gamma,
                                                  const float* __restrict__ beta,
                                                  const float* __restrict__ Wb,
                                                  const float* __restrict__ bg)
{
    extern __shared__ char sm[];
    const u32 sb = smem_u32(sm);
    const int tid = threadIdx.x, wid = tid >> 5, lane = tid & 31;
    const int wr = wid & 7, wc = wid >> 3;
    const size_t r0 = (size_t)blockIdx.x * 128;
    float* xs  = (float*)(sm + LNP_XS);
    float* sWb = (float*)(sm + LNP_WB);

    // 1) load x tile + Wb
    const float4* xg = (const float4*)(x + r0 * CZ);
    for (int i = tid; i < 4096; i += 512) {
        float4 v = xg[i];
        int row = i >> 5, c = (i & 31) << 2;
        float* d = xs + row * 129 + c;
        d[0] = v.x; d[1] = v.y; d[2] = v.z; d[3] = v.w;
    }
    if (tid < 512) sWb[tid] = Wb[tid];
    __syncthreads();

    // 2) LayerNorm (one thread per row)
    if (tid < 128) {
        float* row = xs + tid * 129;
        float s = 0.f, s2 = 0.f;
#pragma unroll 8
        for (int c = 0; c < 128; c++) { float v = row[c]; s += v; s2 += v * v; }
        float mu  = s * (1.f / 128.f);
        float var = s2 * (1.f / 128.f) - mu * mu;
        float inv = rsqrtf(var + 1e-5f);
#pragma unroll 8
        for (int c = 0; c < 128; c++)
            row[c] = (row[c] - mu) * inv * gamma[c] + beta[c];
    }
    __syncthreads();

    // 3) bias projection (fp32 exact): one output per thread
    {
        int row = tid >> 2, h = tid & 3;
        const float* xr = xs + row * 129;
        float s = 0.f;
#pragma unroll 8
        for (int c = 0; c < 128; c++) s += xr[c] * sWb[c * 4 + h];
        g_BiasT[(size_t)h * RTOT + r0 + row] = s;
    }
    // 4) convert A -> split bf16 in smem
    for (int p = tid; p < 8192; p += 512) {
        int row = p >> 6, c = (p & 63) << 1;
        float a0 = xs[row * 129 + c], a1 = xs[row * 129 + c + 1];
        __nv_bfloat16 h0 = __float2bfloat16(a0), h1 = __float2bfloat16(a1);
        __nv_bfloat16 l0 = __float2bfloat16(a0 - __bfloat162float(h0));
        __nv_bfloat16 l1 = __float2bfloat16(a1 - __bfloat162float(h1));
        __nv_bfloat162 hh; hh.x = h0; hh.y = h1;
        __nv_bfloat162 ll; ll.x = l0; ll.y = l1;
        u32 off = (u32)(row * TSTRIDE + c) * 2;
        *(__nv_bfloat162*)(sm + LNP_SA + off)         = hh;
        *(__nv_bfloat162*)(sm + LNP_SA + THALF + off) = ll;
    }
    // prefetch B0 -> buf1
    cp_weights(sb, LNP_SB1, 0, tid);
    __syncthreads();   // xs fully consumed; A visible

    // fragment addressing
    const int i_ = lane >> 3, r_ = lane & 7;
    const u32 aBase = sb + LNP_SA +
        (u32)((wr * 16 + ((i_ & 1) << 3) + r_) * TSTRIDE + ((i_ >> 1) << 3)) * 2;
    const u32 bOffW = (u32)((wc * 64 + ((i_ >> 1) << 3) + r_) * TSTRIDE + ((i_ & 1) << 3)) * 2;
    const int g = lane >> 2, tig = lane & 3;
    const size_t rowA = r0 + wr * 16 + g;
    const size_t rowB = rowA + 8;

#pragma unroll
    for (int m = 0; m < 4; m++) {
        if (m < 3) cp_weights(sb, (m & 1) ? LNP_SB1 : LNP_SB0, m + 1, tid);
        if (m < 3) { CP_WAIT(1); } else { CP_WAIT(0); }
        __syncthreads();

        const u32 bufOff = (m & 1) ? LNP_SB0 : LNP_SB1;   // B(m) lives here
        float acc[8][4];
#pragma unroll
        for (int t = 0; t < 8; t++)
#pragma unroll
            for (int v = 0; v < 4; v++) acc[t][v] = 0.f;

        gemm_warp(acc, aBase, sb + bufOff + bOffW);

        if (m < 3) {
            float* O = (m == 0) ? g_Q : (m == 1) ? g_K : g_V;
#pragma unroll
            for (int nt = 0; nt < 8; nt++) {
                int col = wc * 64 + nt * 8 + tig * 2;
                *(float2*)(O + rowA * CZ + col) = make_float2(acc[nt][0], acc[nt][1]);
                *(float2*)(O + rowB * CZ + col) = make_float2(acc[nt][2], acc[nt][3]);
            }
        } else {
#pragma unroll
            for (int nt = 0; nt < 8; nt++) {
                int col = wc * 64 + nt * 8 + tig * 2;
                float2 bgv = __ldg((const float2*)(bg + col));
                float2 oA, oB;
                oA.x = 1.f / (1.f + __expf(-(acc[nt][0] + bgv.x)));
                oA.y = 1.f / (1.f + __expf(-(acc[nt][1] + bgv.y)));
                oB.x = 1.f / (1.f + __expf(-(acc[nt][2] + bgv.x)));
                oB.y = 1.f / (1.f + __expf(-(acc[nt][3] + bgv.y)));
                *(float2*)(g_G + rowA * CZ + col) = oA;
                *(float2*)(g_G + rowB * CZ + col) = oB;
            }
        }
        __syncthreads();   // buffer safe to overwrite next iter
    }
}

// ---------------------------------------------------------------------------
// Kernel 2: attention via mma.sync split-bf16, flash-style, no-max softmax.
// Grid (256, 8): blockIdx.x = i, blockIdx.y = h*2 + jhalf. 8 warps x 16 j-rows.
// ---------------------------------------------------------------------------
#define AT_KHI 0
#define AT_KLO 20480
#define AT_VHI 40960
#define AT_VLO (40960 + 16896)
#define AT_SMEM (40960 + 2 * 16896)
#define KSTR 40
#define VSTR 264

__global__ __launch_bounds__(256, 2) void attn_mma()
{
    extern __shared__ char sm[];
    const u32 sb = smem_u32(sm);
    const int tid = threadIdx.x, wid = tid >> 5, lane = tid & 31;
    const int bi = blockIdx.x;
    const int h  = blockIdx.y >> 1;
    const int jh = blockIdx.y & 1;
    const size_t base = ((size_t)bi * NSEQ) * CZ + (size_t)h * HD;

    __nv_bfloat16* KhiS = (__nv_bfloat16*)(sm + AT_KHI);
    __nv_bfloat16* KloS = (__nv_bfloat16*)(sm + AT_KLO);
    __nv_bfloat16* VhiS = (__nv_bfloat16*)(sm + AT_VHI);
    __nv_bfloat16* VloS = (__nv_bfloat16*)(sm + AT_VLO);

    for (int e = tid; e < 2048; e += 256) {
        int k = e >> 3, d4 = (e & 7) << 2;
        float4 kv = *(const float4*)(g_K + base + (size_t)k * CZ + d4);
        float4 vv = *(const float4*)(g_V + base + (size_t)k * CZ + d4);
        float kf[4] = {kv.x, kv.y, kv.z, kv.w};
        float vf[4] = {vv.x, vv.y, vv.z, vv.w};
#pragma unroll
        for (int m = 0; m < 4; m++) {
            __nv_bfloat16 kh = __float2bfloat16(kf[m]);
            KhiS[k * KSTR + d4 + m] = kh;
            KloS[k * KSTR + d4 + m] = __float2bfloat16(kf[m] - __bfloat162float(kh));
            __nv_bfloat16 vh = __float2bfloat16(vf[m]);
            VhiS[(d4 + m) * VSTR + k] = vh;
            VloS[(d4 + m) * VSTR + k] = __float2bfloat16(vf[m] - __bfloat162float(vh));
        }
    }
    __syncthreads();

    const int jr = jh * 128 + wid * 16;
    const int r  = lane >> 2, c2 = (lane & 3) << 1;
    const float scale = 0.17677669529663689f;

    u32 qhi[2][4], qlo[2][4];
#pragma unroll
    for (int ks = 0; ks < 2; ks++)
#pragma unroll
        for (int reg = 0; reg < 4; reg++) {
            int row = jr + r + (reg & 1) * 8;
            int col = ks * 16 + c2 + ((reg >> 1) << 3);
            float2 qv = *(const float2*)(g_Q + base + (size_t)row * CZ + col);
            qv.x *= scale; qv.y *= scale;
            float hx = __bfloat162float(__float2bfloat16(qv.x));
            float hy = __bfloat162float(__float2bfloat16(qv.y));
            qhi[ks][reg] = pack_bf2(qv.x, qv.y);
            qlo[ks][reg] = pack_bf2(qv.x - hx, qv.y - hy);
        }

    const int i_ = lane >> 3, r_ = lane & 7;
    const int brow = ((i_ >> 1) << 3) + r_;
    const int bcol = (i_ & 1) << 3;

    float oacc[4][4];
#pragma unroll
    for (int t = 0; t < 4; t++)
#pragma unroll
        for (int v = 0; v < 4; v++) oacc[t][v] = 0.f;
    float lsum0 = 0.f, lsum1 = 0.f;

    const float* bias0 = g_BiasT + (size_t)h * RTOT + (size_t)(jr + r) * NSEQ;
    const float* bias1 = bias0 + 8 * NSEQ;

    for (int kc = 0; kc < 4; kc++) {
        float sacc[8][4];
#pragma unroll
        for (int t = 0; t < 8; t++)
#pragma unroll
            for (int v = 0; v < 4; v++) sacc[t][v] = 0.f;

#pragma unroll
        for (int p4 = 0; p4 < 4; p4++) {
#pragma unroll
            for (int ks = 0; ks < 2; ks++) {
                u32 addr = sb + AT_KHI + (u32)((kc * 64 + p4 * 16 + brow) * KSTR + ks * 16 + bcol) * 2;
                u32 bh[4], bl[4];
                ldsm_x4(bh, addr);
                ldsm_x4(bl, addr + (AT_KLO - AT_KHI));
                mma_bf16(sacc[2 * p4],     qhi[ks], bh);
                mma_bf16(sacc[2 * p4 + 1], qhi[ks], bh + 2);
                mma_bf16(sacc[2 * p4],     qlo[ks], bh);
                mma_bf16(sacc[2 * p4 + 1], qlo[ks], bh + 2);
                mma_bf16(sacc[2 * p4],     qhi[ks], bl);
                mma_bf16(sacc[2 * p4 + 1], qhi[ks], bl + 2);
            }
        }

#pragma unroll
        for (int nt = 0; nt < 8; nt++) {
            int kcol = kc * 64 + nt * 8 + c2;
            float2 b0 = __ldg((const float2*)(bias0 + kcol));
            float2 b1 = __ldg((const float2*)(bias1 + kcol));
            float p00 = __expf(sacc[nt][0] + b0.x);
            float p01 = __expf(sacc[nt][1] + b0.y);
            float p10 = __expf(sacc[nt][2] + b1.x);
            float p11 = __expf(sacc[nt][3] + b1.y);
            sacc[nt][0] = p00; sacc[nt][1] = p01;
            sacc[nt][2] = p10; sacc[nt][3] = p11;
            lsum0 += p00 + p01;
            lsum1 += p10 + p11;
        }

#pragma unroll
        for (int ks2 = 0; ks2 < 4; ks2++) {
            u32 phi[4], plo[4];
            {
                const float* s0 = sacc[2 * ks2];
                const float* s1 = sacc[2 * ks2 + 1];
                float h00 = __bfloat162float(__float2bfloat16(s0[0]));
                float h01 = __bfloat162float(__float2bfloat16(s0[1]));
                float h02 = __bfloat162float(__float2bfloat16(s0[2]));
                float h03 = __bfloat162float(__float2bfloat16(s0[3]));
                float h10 = __bfloat162float(__float2bfloat16(s1[0]));
                float h11 = __bfloat162float(__float2bfloat16(s1[1]));
                float h12 = __bfloat162float(__float2bfloat16(s1[2]));
                float h13 = __bfloat162float(__float2bfloat16(s1[3]));
                phi[0] = pack_bf2(s0[0], s0[1]);
                phi[1] = pack_bf2(s0[2], s0[3]);
                phi[2] = pack_bf2(s1[0], s1[1]);
                phi[3] = pack_bf2(s1[2], s1[3]);
                plo[0] = pack_bf2(s0[0] - h00, s0[1] - h01);
                plo[1] = pack_bf2(s0[2] - h02, s0[3] - h03);
                plo[2] = pack_bf2(s1[0] - h10, s1[1] - h11);
                plo[3] = pack_bf2(s1[2] - h12, s1[3] - h13);
            }
            u32 vh[8], vl[8];
            u32 a0 = sb + AT_VHI + (u32)(brow * VSTR + kc * 64 + ks2 * 16 + bcol) * 2;
            u32 a1 = sb + AT_VHI + (u32)((brow + 16) * VSTR + kc * 64 + ks2 * 16 + bcol) * 2;
            ldsm_x4(vh,     a0);
            ldsm_x4(vh + 4, a1);
            ldsm_x4(vl,     a0 + (AT_VLO - AT_VHI));
            ldsm_x4(vl + 4, a1 + (AT_VLO - AT_VHI));
#pragma unroll
            for (int ntd = 0; ntd < 4; ntd++) {
                mma_bf16(oacc[ntd], phi, vh + 2 * ntd);
                mma_bf16(oacc[ntd], plo, vh + 2 * ntd);
                mma_bf16(oacc[ntd], phi, vl + 2 * ntd);
            }
        }
    }

    lsum0 += __shfl_xor_sync(0xFFFFFFFF, lsum0, 1);
    lsum0 += __shfl_xor_sync(0xFFFFFFFF, lsum0, 2);
    lsum1 += __shfl_xor_sync(0xFFFFFFFF, lsum1, 1);
    lsum1 += __shfl_xor_sync(0xFFFFFFFF, lsum1, 2);
    const float inv0 = __fdividef(1.f, lsum0);
    const float inv1 = __fdividef(1.f, lsum1);

    const size_t row0 = base + (size_t)(jr + r) * CZ;
    const size_t row1 = row0 + 8 * CZ;
#pragma unroll
    for (int ntd = 0; ntd < 4; ntd++) {
        int col = ntd * 8 + c2;
        float2 g0 = __ldg((const float2*)(g_G + row0 + col));
        float2 g1 = __ldg((const float2*)(g_G + row1 + col));
        float2 o0, o1;
        o0.x = oacc[ntd][0] * inv0 * g0.x;
        o0.y = oacc[ntd][1] * inv0 * g0.y;
        o1.x = oacc[ntd][2] * inv1 * g1.x;
        o1.y = oacc[ntd][3] * inv1 * g1.y;
        *(float2*)(g_AV + row0 + col) = o0;
        *(float2*)(g_AV + row1 + col) = o1;
    }
}

// ---------------------------------------------------------------------------
// Kernel 3: output projection, 512 threads, A reloaded per ks
// ---------------------------------------------------------------------------
__global__ __launch_bounds__(512) void outproj_mma(const float* __restrict__ bo_,
                                                   float* __restrict__ out)
{
    extern __shared__ char sm[];
    const u32 sb = smem_u32(sm);
    const int tid = threadIdx.x, wid = tid >> 5, lane = tid & 31;
    const int wr = wid & 7, wc = wid >> 3;
    const size_t r0 = (size_t)blockIdx.x * 128;

    // prefetch B (Wo split) via cp.async, overlap with A conversion
    cp_weights(sb, OP_SB, 4, tid);

    for (int p = tid; p < 8192; p += 512) {
        int row = p >> 6, c = (p & 63) << 1;
        float2 v = *(const float2*)(g_AV + (r0 + row) * CZ + c);
        __nv_bfloat16 h0 = __float2bfloat16(v.x), h1 = __float2bfloat16(v.y);
        __nv_bfloat16 l0 = __float2bfloat16(v.x - __bfloat162float(h0));
        __nv_bfloat16 l1 = __float2bfloat16(v.y - __bfloat162float(h1));
        __nv_bfloat162 hh; hh.x = h0; hh.y = h1;
        __nv_bfloat162 ll; ll.x = l0; ll.y = l1;
        u32 off = (u32)(row * TSTRIDE + c) * 2;
        *(__nv_bfloat162*)(sm + OP_SA + off)         = hh;
        *(__nv_bfloat162*)(sm + OP_SA + THALF + off) = ll;
    }
    CP_WAIT(0);
    __syncthreads();

    const int i_ = lane >> 3, r_ = lane & 7;
    const u32 aBase = sb + OP_SA +
        (u32)((wr * 16 + ((i_ & 1) << 3) + r_) * TSTRIDE + ((i_ >> 1) << 3)) * 2;
    const u32 bBase = sb + OP_SB +
        (u32)((wc * 64 + ((i_ >> 1) << 3) + r_) * TSTRIDE + ((i_ & 1) << 3)) * 2;

    float acc[8][4];
#pragma unroll
    for (int t = 0; t < 8; t++)
#pragma unroll
        for (int v = 0; v < 4; v++) acc[t][v] = 0.f;

    gemm_warp(acc, aBase, bBase);

    const int g = lane >> 2, tig = lane & 3;
    const size_t rowA = r0 + wr * 16 + g;
    const size_t rowB = rowA + 8;
#pragma unroll
    for (int nt = 0; nt < 8; nt++) {
        int col = wc * 64 + nt * 8 + tig * 2;
        float2 bov = __ldg((const float2*)(bo_ + col));
        *(float2*)(out + rowA * CZ + col) = make_float2(acc[nt][0] + bov.x, acc[nt][1] + bov.y);
        *(float2*)(out + rowB * CZ + col) = make_float2(acc[nt][2] + bov.x, acc[nt][3] + bov.y);
    }
}

// ---------------------------------------------------------------------------
extern "C" void kernel_launch(void* const* d_in, const int* in_sizes, int n_in,
                              void* d_out, int out_size)
{
    const float* x     = (const float*)d_in[0];
    const float* gamma = (const float*)d_in[1];
    const float* beta  = (const float*)d_in[2];
    const float* Wq    = (const float*)d_in[3];
    const float* Wk    = (const float*)d_in[4];
    const float* Wv    = (const float*)d_in[5];
    const float* Wb    = (const float*)d_in[6];
    const float* Wg    = (const float*)d_in[7];
    const float* bg    = (const float*)d_in[8];
    const float* Wo    = (const float*)d_in[9];
    const float* bo    = (const float*)d_in[10];
    float* out = (float*)d_out;

    cudaFuncSetAttribute(lnproj_mma,  cudaFuncAttributeMaxDynamicSharedMemorySize, LNP_SMEM);
    cudaFuncSetAttribute(outproj_mma, cudaFuncAttributeMaxDynamicSharedMemorySize, OP_SMEM);
    cudaFuncSetAttribute(attn_mma,    cudaFuncAttributeMaxDynamicSharedMemorySize, AT_SMEM);

    wtransform<<<5, 256>>>(Wq, Wk, Wv, Wg, Wo);
    lnproj_mma<<<RTOT / 128, 512, LNP_SMEM>>>(x, gamma, beta, Wb, bg);
    dim3 g2(NSEQ, 2 * NH);
    attn_mma<<<g2, 256, AT_SMEM>>>();
    outproj_mma<<<RTOT / 128, 512, OP_SMEM>>>(bo, out);
}